// round 12
// baseline (speedup 1.0000x reference)
#include <cuda_runtime.h>
#include <cuda_fp16.h>
#include <math.h>

#define NN 50000
#define FF 128
#define NE 800000
#define NT 5000
#define NWF 4096               // 8 ksteps * 16 ntiles * 32 lanes
#define SCAT_T (NE / 2)        // 400000 scatter threads (2 edges each)
#define MEFF_T (NN * 32)       // 1600000 meff quad threads
#define MAXDEG 128             // padded CSR row capacity (P(overflow) ~ 1e-68)
#define GROWS 64               // rows per fused block
#define HS_STRIDE 136          // padded fp16 row stride in smem

// ---------------- static device scratch (no allocations allowed) ----------------
struct __align__(16) H2x4 { __half2 me01, me23, mx01, mx23; };
static __device__ H2x4  g_P[NN * 32];          // packed (Me, Mx) fp16, 25.6 MB
static __device__ uint2 g_Wf[NWF];             // W fp16 in mma B-fragment layout, 32 KB
static __device__ int   g_cnt[NN];             // degree counter / CSR fill cursor
static __device__ int2  g_cv[NN * MAXDEG];     // padded CSR (col, val-bits), 51.2 MB

// ---------------- helpers ----------------
__device__ __forceinline__ float sigmoid_fast(float z) {
    return 1.0f / (1.0f + __expf(-z));
}
__device__ __forceinline__ float elu1(float v) {
    return v > 0.0f ? v : expm1f(v);
}
__device__ __forceinline__ void ldm_x4(unsigned& r0, unsigned& r1, unsigned& r2, unsigned& r3,
                                       unsigned addr) {
    asm volatile("ldmatrix.sync.aligned.m8n8.x4.shared.b16 {%0,%1,%2,%3}, [%4];"
                 : "=r"(r0), "=r"(r1), "=r"(r2), "=r"(r3) : "r"(addr));
}
__device__ __forceinline__ void mma16816(float* c, const unsigned* a, unsigned b0, unsigned b1) {
    asm volatile(
        "mma.sync.aligned.m16n8k16.row.col.f32.f16.f16.f32 "
        "{%0,%1,%2,%3}, {%4,%5,%6,%7}, {%8,%9}, {%0,%1,%2,%3};"
        : "+f"(c[0]), "+f"(c[1]), "+f"(c[2]), "+f"(c[3])
        : "r"(a[0]), "r"(a[1]), "r"(a[2]), "r"(a[3]), "r"(b0), "r"(b1));
}
// fp32 single-edge accumulate (tail path, exact)
__device__ __forceinline__ void acc_edge(int col, float w, int lane, float4& d, float4& h) {
    H2x4 p = g_P[col * 32 + lane];
    float2 a, b;
    a = __half22float2(p.me01); b = __half22float2(p.me23);
    d.x += a.x; d.y += a.y; d.z += b.x; d.w += b.y;
    a = __half22float2(p.mx01); b = __half22float2(p.mx23);
    h.x += w * a.x; h.y += w * a.y; h.z += w * b.x; h.w += w * b.y;
}
// fp16 packed single-edge accumulate (hot path)
__device__ __forceinline__ void acc_edge_h(int col, float w, int lane,
                                           __half2& d01, __half2& d23,
                                           __half2& h01, __half2& h23) {
    H2x4 p = g_P[col * 32 + lane];
    __half2 wh = __float2half2_rn(w);
    d01 = __hadd2(d01, p.me01);
    d23 = __hadd2(d23, p.me23);
    h01 = __hfma2(p.mx01, wh, h01);
    h23 = __hfma2(p.mx23, wh, h23);
}
// process one 4-edge group (2 int4s) with fp16 accumulation, flush to fp32
__device__ __forceinline__ void acc_group(int4 q0, int4 q1, int lane, float4& d, float4& h) {
    __half2 z   = __float2half2_rn(0.f);
    __half2 d01 = z, d23 = z, h01 = z, h23 = z;
    acc_edge_h(q0.x, __int_as_float(q0.y), lane, d01, d23, h01, h23);
    acc_edge_h(q0.z, __int_as_float(q0.w), lane, d01, d23, h01, h23);
    acc_edge_h(q1.x, __int_as_float(q1.y), lane, d01, d23, h01, h23);
    acc_edge_h(q1.z, __int_as_float(q1.w), lane, d01, d23, h01, h23);
    float2 f;
    f = __half22float2(d01); d.x += f.x; d.y += f.y;
    f = __half22float2(d23); d.z += f.x; d.w += f.y;
    f = __half22float2(h01); h.x += f.x; h.y += f.y;
    f = __half22float2(h23); h.z += f.x; h.w += f.y;
}
// normalize + pack one output row quad
__device__ __forceinline__ void store_row(__half* hdst, float4 d, float4 h) {
    float4 o;
    o.x = (d.x != 0.f) ? h.x * __fdividef(1.f, d.x) : 0.f;
    o.y = (d.y != 0.f) ? h.y * __fdividef(1.f, d.y) : 0.f;
    o.z = (d.z != 0.f) ? h.z * __fdividef(1.f, d.z) : 0.f;
    o.w = (d.w != 0.f) ? h.w * __fdividef(1.f, d.w) : 0.f;
    __half2 h01 = __floats2half2_rn(o.x, o.y);
    __half2 h23 = __floats2half2_rn(o.z, o.w);
    uint2 ph;
    ph.x = *(const unsigned*)&h01;
    ph.y = *(const unsigned*)&h23;
    *(uint2*)hdst = ph;
}

// ---------------- kernels ----------------
// L1: zero degree counters + build W mma-fragment table
__global__ void k_init(const float* __restrict__ W) {
    int i = blockIdx.x * blockDim.x + threadIdx.x;
    if (i < NN) g_cnt[i] = 0;
    int j = i - NN;
    if (j >= 0 && j < NWF) {
        int lane = j & 31, ntg = (j >> 5) & 15, ks = j >> 9;
        int n  = ntg * 8 + (lane >> 2);
        int tq = lane & 3;
        int k0 = ks * 16 + tq * 2;
        __half2 b0 = __floats2half2_rn(W[k0 * FF + n],       W[(k0 + 1) * FF + n]);
        __half2 b1 = __floats2half2_rn(W[(k0 + 8) * FF + n], W[(k0 + 9) * FF + n]);
        uint2 o;
        o.x = *(const unsigned*)&b0;
        o.y = *(const unsigned*)&b1;
        g_Wf[j] = o;
    }
}

// L2: single-pass padded-CSR scatter (atomics) overlapped with meff gating (DRAM-bound)
__global__ void k_scatter_meff(const int* __restrict__ erow, const int* __restrict__ ecol,
                               const float* __restrict__ aval,
                               const float* __restrict__ x, const float* __restrict__ M) {
    int gi = blockIdx.x * blockDim.x + threadIdx.x;
    if (gi < SCAT_T) {
        int2   r = ((const int2*)erow)[gi];
        int2   c = ((const int2*)ecol)[gi];
        float2 w = ((const float2*)aval)[gi];
        int p0 = atomicAdd(&g_cnt[r.x], 1);
        if (p0 < MAXDEG) g_cv[r.x * MAXDEG + p0] = make_int2(c.x, __float_as_int(w.x));
        int p1 = atomicAdd(&g_cnt[r.y], 1);
        if (p1 < MAXDEG) g_cv[r.y * MAXDEG + p1] = make_int2(c.y, __float_as_int(w.y));
        return;
    }
    int i = gi - SCAT_T;
    if (i >= MEFF_T) return;
    float4 m  = ((const float4*)M)[i];
    float4 xv = ((const float4*)x)[i];
    float4 me, mx;
    me.x = sigmoid_fast(m.x); me.y = sigmoid_fast(m.y);
    me.z = sigmoid_fast(m.z); me.w = sigmoid_fast(m.w);
    mx.x = me.x * xv.x; mx.y = me.y * xv.y;
    mx.z = me.z * xv.z; mx.w = me.w * xv.w;
    H2x4 p;
    p.me01 = __floats2half2_rn(me.x, me.y);
    p.me23 = __floats2half2_rn(me.z, me.w);
    p.mx01 = __floats2half2_rn(mx.x, mx.y);
    p.mx23 = __floats2half2_rn(mx.z, mx.w);
    g_P[i] = p;
}

// L3: overwrite train rows with (Me=1, Mx=x). Duplicate ids write identical data.
__global__ void k_fix(const int* __restrict__ tid, const float* __restrict__ x) {
    int i = blockIdx.x * blockDim.x + threadIdx.x;
    if (i >= NT * 32) return;
    int node = tid[i >> 5];
    int lane = i & 31;
    float4 xv = *(const float4*)&x[node * FF + lane * 4];
    H2x4 p;
    p.me01 = __floats2half2_rn(1.f, 1.f);
    p.me23 = __floats2half2_rn(1.f, 1.f);
    p.mx01 = __floats2half2_rn(xv.x, xv.y);
    p.mx23 = __floats2half2_rn(xv.z, xv.w);
    g_P[node * 32 + lane] = p;
}

// L4 (fused): gather 64 rows into smem — 2 rows interleaved per warp for MLP —
// then out = elu(Hs @ W) via mma.sync.
__global__ void __launch_bounds__(256, 4) k_gg(float* __restrict__ out) {
    __shared__ __half Hs[GROWS * HS_STRIDE];
    int r0 = blockIdx.x * GROWS;
    int t  = threadIdx.x;
    int wid = t >> 5, lane = t & 31;

    // ---- phase 1: gather-reduce 8 rows per warp, processed as 4 row-pairs ----
    for (int p = 0; p < 4; p++) {
        int lra  = wid * 8 + p * 2;
        int rowa = r0 + lra, rowb = rowa + 1;
        int dega = 0, degb = 0;
        if (rowa < NN) { dega = g_cnt[rowa]; if (dega > MAXDEG) dega = MAXDEG; }
        if (rowb < NN) { degb = g_cnt[rowb]; if (degb > MAXDEG) degb = MAXDEG; }
        const int4* cpa = (const int4*)&g_cv[(size_t)rowa * MAXDEG];
        const int4* cpb = (const int4*)&g_cv[(size_t)rowb * MAXDEG];
        float4 da = make_float4(0.f, 0.f, 0.f, 0.f), ha = da;
        float4 db = da, hb = da;
        int nqa = dega >> 2, nqb = degb >> 2;
        int nq = nqa > nqb ? nqa : nqb;
        for (int q = 0; q < nq; q++) {
            int4 a0, a1, b0, b1;
            bool va = q < nqa, vb = q < nqb;
            if (va) { a0 = __ldg(&cpa[2 * q]); a1 = __ldg(&cpa[2 * q + 1]); }
            if (vb) { b0 = __ldg(&cpb[2 * q]); b1 = __ldg(&cpb[2 * q + 1]); }
            if (va) acc_group(a0, a1, lane, da, ha);
            if (vb) acc_group(b0, b1, lane, db, hb);
        }
        for (int j = nqa << 2; j < dega; ++j) {
            int2 cv = __ldg(&g_cv[(size_t)rowa * MAXDEG + j]);
            acc_edge(cv.x, __int_as_float(cv.y), lane, da, ha);
        }
        for (int j = nqb << 2; j < degb; ++j) {
            int2 cv = __ldg(&g_cv[(size_t)rowb * MAXDEG + j]);
            acc_edge(cv.x, __int_as_float(cv.y), lane, db, hb);
        }
        store_row(&Hs[lra * HS_STRIDE + lane * 4], da, ha);
        store_row(&Hs[(lra + 1) * HS_STRIDE + lane * 4], db, hb);
    }
    __syncthreads();

    // ---- phase 2: mma GEMM on the smem tile ----
    int wm = wid >> 1, wn = wid & 1;
    int sub = lane >> 3, rr8 = lane & 7;
    int arow = wm * 16 + rr8 + (sub & 1) * 8;
    int acol = (sub >> 1) * 8;

    float acc[8][4] = {};
    #pragma unroll
    for (int ks = 0; ks < 8; ks++) {
        unsigned a[4];
        unsigned addr = (unsigned)__cvta_generic_to_shared(&Hs[arow * HS_STRIDE + ks * 16 + acol]);
        ldm_x4(a[0], a[1], a[2], a[3], addr);
        #pragma unroll
        for (int nt = 0; nt < 8; nt++) {
            uint2 b = __ldg(&g_Wf[(ks * 16 + wn * 8 + nt) * 32 + lane]);
            mma16816(acc[nt], a, b.x, b.y);
        }
    }

    int g = lane >> 2, tq = lane & 3;
    int row0 = r0 + wm * 16 + g;
    int row1 = row0 + 8;
    #pragma unroll
    for (int nt = 0; nt < 8; nt++) {
        int col = wn * 64 + nt * 8 + 2 * tq;
        if (row0 < NN) {
            float2 v;
            v.x = elu1(acc[nt][0]);
            v.y = elu1(acc[nt][1]);
            *(float2*)&out[row0 * FF + col] = v;
        }
        if (row1 < NN) {
            float2 v;
            v.x = elu1(acc[nt][2]);
            v.y = elu1(acc[nt][3]);
            *(float2*)&out[row1 * FF + col] = v;
        }
    }
}

// ---------------- launch ----------------
extern "C" void kernel_launch(void* const* d_in, const int* in_sizes, int n_in,
                              void* d_out, int out_size) {
    const float* x    = (const float*)d_in[0];
    const int*   erow = (const int*)  d_in[1];
    const int*   ecol = (const int*)  d_in[2];
    const float* aval = (const float*)d_in[3];
    const int*   tid  = (const int*)  d_in[4];
    const float* M    = (const float*)d_in[5];
    const float* W    = (const float*)d_in[6];
    float*       out  = (float*)d_out;

    k_init        <<<(NN + NWF + 255) / 256, 256>>>(W);
    k_scatter_meff<<<(SCAT_T + MEFF_T + 255) / 256, 256>>>(erow, ecol, aval, x, M);
    k_fix         <<<(NT * 32 + 255) / 256, 256>>>(tid, x);
    k_gg          <<<(NN + GROWS - 1) / GROWS, 256>>>(out);
}

// round 13
// speedup vs baseline: 1.0956x; 1.0956x over previous
#include <cuda_runtime.h>
#include <cuda_fp16.h>
#include <math.h>

#define NN 50000
#define FF 128
#define NE 800000
#define NT 5000
#define NWF 4096               // 8 ksteps * 16 ntiles * 32 lanes
#define SCAT_T (NE / 2)        // 400000 scatter threads (2 edges each)
#define MEFF_T (NN * 32)       // 1600000 meff quad threads
#define MAXDEG 128             // padded CSR row capacity (P(overflow) ~ 1e-68)
#define GROWS 64               // rows per fused block
#define HS_STRIDE 136          // padded fp16 row stride in smem

// ---------------- static device scratch (no allocations allowed) ----------------
struct __align__(16) H2x4 { __half2 me01, me23, mx01, mx23; };
static __device__ H2x4  g_P[NN * 32];          // packed (Me, Mx) fp16, 25.6 MB
static __device__ uint2 g_Wf[NWF];             // W fp16 in mma B-fragment layout, 32 KB
static __device__ int   g_cnt[NN];             // degree counter / CSR fill cursor
static __device__ int2  g_cv[NN * MAXDEG];     // padded CSR (col, val-bits), 51.2 MB

// ---------------- helpers ----------------
__device__ __forceinline__ float sigmoid_fast(float z) {
    return 1.0f / (1.0f + __expf(-z));
}
__device__ __forceinline__ float elu1(float v) {
    return v > 0.0f ? v : expm1f(v);
}
__device__ __forceinline__ void ldm_x4(unsigned& r0, unsigned& r1, unsigned& r2, unsigned& r3,
                                       unsigned addr) {
    asm volatile("ldmatrix.sync.aligned.m8n8.x4.shared.b16 {%0,%1,%2,%3}, [%4];"
                 : "=r"(r0), "=r"(r1), "=r"(r2), "=r"(r3) : "r"(addr));
}
__device__ __forceinline__ void mma16816(float* c, const unsigned* a, unsigned b0, unsigned b1) {
    asm volatile(
        "mma.sync.aligned.m16n8k16.row.col.f32.f16.f16.f32 "
        "{%0,%1,%2,%3}, {%4,%5,%6,%7}, {%8,%9}, {%0,%1,%2,%3};"
        : "+f"(c[0]), "+f"(c[1]), "+f"(c[2]), "+f"(c[3])
        : "r"(a[0]), "r"(a[1]), "r"(a[2]), "r"(a[3]), "r"(b0), "r"(b1));
}
// accumulate one preloaded edge payload: d += Me, h += w * Mx  (fp32, exact)
__device__ __forceinline__ void acc_p(const H2x4& p, float w, float4& d, float4& h) {
    float2 a, b;
    a = __half22float2(p.me01); b = __half22float2(p.me23);
    d.x += a.x; d.y += a.y; d.z += b.x; d.w += b.y;
    a = __half22float2(p.mx01); b = __half22float2(p.mx23);
    h.x += w * a.x; h.y += w * a.y; h.z += w * b.x; h.w += w * b.y;
}
// load+accumulate single edge (tail path)
__device__ __forceinline__ void acc_edge(int col, float w, int lane, float4& d, float4& h) {
    H2x4 p = g_P[col * 32 + lane];
    acc_p(p, w, d, h);
}

// ---------------- kernels ----------------
// L1: zero degree counters + build W mma-fragment table
__global__ void k_init(const float* __restrict__ W) {
    int i = blockIdx.x * blockDim.x + threadIdx.x;
    if (i < NN) g_cnt[i] = 0;
    int j = i - NN;
    if (j >= 0 && j < NWF) {
        int lane = j & 31, ntg = (j >> 5) & 15, ks = j >> 9;
        int n  = ntg * 8 + (lane >> 2);
        int tq = lane & 3;
        int k0 = ks * 16 + tq * 2;
        __half2 b0 = __floats2half2_rn(W[k0 * FF + n],       W[(k0 + 1) * FF + n]);
        __half2 b1 = __floats2half2_rn(W[(k0 + 8) * FF + n], W[(k0 + 9) * FF + n]);
        uint2 o;
        o.x = *(const unsigned*)&b0;
        o.y = *(const unsigned*)&b1;
        g_Wf[j] = o;
    }
}

// L2: single-pass padded-CSR scatter (atomics) overlapped with meff gating (DRAM-bound)
__global__ void k_scatter_meff(const int* __restrict__ erow, const int* __restrict__ ecol,
                               const float* __restrict__ aval,
                               const float* __restrict__ x, const float* __restrict__ M) {
    int gi = blockIdx.x * blockDim.x + threadIdx.x;
    if (gi < SCAT_T) {
        int2   r = ((const int2*)erow)[gi];
        int2   c = ((const int2*)ecol)[gi];
        float2 w = ((const float2*)aval)[gi];
        int p0 = atomicAdd(&g_cnt[r.x], 1);
        if (p0 < MAXDEG) g_cv[r.x * MAXDEG + p0] = make_int2(c.x, __float_as_int(w.x));
        int p1 = atomicAdd(&g_cnt[r.y], 1);
        if (p1 < MAXDEG) g_cv[r.y * MAXDEG + p1] = make_int2(c.y, __float_as_int(w.y));
        return;
    }
    int i = gi - SCAT_T;
    if (i >= MEFF_T) return;
    float4 m  = ((const float4*)M)[i];
    float4 xv = ((const float4*)x)[i];
    float4 me, mx;
    me.x = sigmoid_fast(m.x); me.y = sigmoid_fast(m.y);
    me.z = sigmoid_fast(m.z); me.w = sigmoid_fast(m.w);
    mx.x = me.x * xv.x; mx.y = me.y * xv.y;
    mx.z = me.z * xv.z; mx.w = me.w * xv.w;
    H2x4 p;
    p.me01 = __floats2half2_rn(me.x, me.y);
    p.me23 = __floats2half2_rn(me.z, me.w);
    p.mx01 = __floats2half2_rn(mx.x, mx.y);
    p.mx23 = __floats2half2_rn(mx.z, mx.w);
    g_P[i] = p;
}

// L3: overwrite train rows with (Me=1, Mx=x). Duplicate ids write identical data.
__global__ void k_fix(const int* __restrict__ tid, const float* __restrict__ x) {
    int i = blockIdx.x * blockDim.x + threadIdx.x;
    if (i >= NT * 32) return;
    int node = tid[i >> 5];
    int lane = i & 31;
    float4 xv = *(const float4*)&x[node * FF + lane * 4];
    H2x4 p;
    p.me01 = __floats2half2_rn(1.f, 1.f);
    p.me23 = __floats2half2_rn(1.f, 1.f);
    p.mx01 = __floats2half2_rn(xv.x, xv.y);
    p.mx23 = __floats2half2_rn(xv.z, xv.w);
    g_P[node * 32 + lane] = p;
}

// L4 (fused): gather 64 rows into smem (8-edge deep unroll for MLP), then
// out = elu(Hs @ W) via mma.sync. 256 thr / 8 warps; gather warp owns 8 rows.
__global__ void __launch_bounds__(256, 4) k_gg(float* __restrict__ out) {
    __shared__ __half Hs[GROWS * HS_STRIDE];
    int r0 = blockIdx.x * GROWS;
    int t  = threadIdx.x;
    int wid = t >> 5, lane = t & 31;

    // ---- phase 1: gather-reduce 8 rows per warp ----
    for (int rr = 0; rr < 8; rr++) {
        int lr  = wid * 8 + rr;
        int row = r0 + lr;
        __half* hdst = &Hs[lr * HS_STRIDE + lane * 4];
        if (row >= NN) {
            *(uint2*)hdst = make_uint2(0u, 0u);
            continue;
        }
        int deg = g_cnt[row];
        if (deg > MAXDEG) deg = MAXDEG;
        const int4* cp = (const int4*)&g_cv[row * MAXDEG];   // 2 edges per int4
        float4 d = make_float4(0.f, 0.f, 0.f, 0.f);
        float4 h = make_float4(0.f, 0.f, 0.f, 0.f);
        int j = 0;
        // 8-edge groups: 4 index LDGs + 8 payload LDG.128s all independent
        for (; j + 7 < deg; j += 8) {
            int q = j >> 1;
            int4 q0 = __ldg(&cp[q]);
            int4 q1 = __ldg(&cp[q + 1]);
            int4 q2 = __ldg(&cp[q + 2]);
            int4 q3 = __ldg(&cp[q + 3]);
            H2x4 p0 = g_P[q0.x * 32 + lane];
            H2x4 p1 = g_P[q0.z * 32 + lane];
            H2x4 p2 = g_P[q1.x * 32 + lane];
            H2x4 p3 = g_P[q1.z * 32 + lane];
            H2x4 p4 = g_P[q2.x * 32 + lane];
            H2x4 p5 = g_P[q2.z * 32 + lane];
            H2x4 p6 = g_P[q3.x * 32 + lane];
            H2x4 p7 = g_P[q3.z * 32 + lane];
            acc_p(p0, __int_as_float(q0.y), d, h);
            acc_p(p1, __int_as_float(q0.w), d, h);
            acc_p(p2, __int_as_float(q1.y), d, h);
            acc_p(p3, __int_as_float(q1.w), d, h);
            acc_p(p4, __int_as_float(q2.y), d, h);
            acc_p(p5, __int_as_float(q2.w), d, h);
            acc_p(p6, __int_as_float(q3.y), d, h);
            acc_p(p7, __int_as_float(q3.w), d, h);
        }
        // 4-edge group
        if (j + 3 < deg) {
            int q = j >> 1;
            int4 q0 = __ldg(&cp[q]);
            int4 q1 = __ldg(&cp[q + 1]);
            H2x4 p0 = g_P[q0.x * 32 + lane];
            H2x4 p1 = g_P[q0.z * 32 + lane];
            H2x4 p2 = g_P[q1.x * 32 + lane];
            H2x4 p3 = g_P[q1.z * 32 + lane];
            acc_p(p0, __int_as_float(q0.y), d, h);
            acc_p(p1, __int_as_float(q0.w), d, h);
            acc_p(p2, __int_as_float(q1.y), d, h);
            acc_p(p3, __int_as_float(q1.w), d, h);
            j += 4;
        }
        // 2-edge group
        if (j + 1 < deg) {
            int4 q0 = __ldg(&cp[j >> 1]);
            H2x4 p0 = g_P[q0.x * 32 + lane];
            H2x4 p1 = g_P[q0.z * 32 + lane];
            acc_p(p0, __int_as_float(q0.y), d, h);
            acc_p(p1, __int_as_float(q0.w), d, h);
            j += 2;
        }
        // last edge
        if (j < deg) {
            int2 cv = __ldg(&g_cv[row * MAXDEG + j]);
            acc_edge(cv.x, __int_as_float(cv.y), lane, d, h);
        }
        float4 o;
        o.x = (d.x != 0.f) ? h.x * __fdividef(1.f, d.x) : 0.f;
        o.y = (d.y != 0.f) ? h.y * __fdividef(1.f, d.y) : 0.f;
        o.z = (d.z != 0.f) ? h.z * __fdividef(1.f, d.z) : 0.f;
        o.w = (d.w != 0.f) ? h.w * __fdividef(1.f, d.w) : 0.f;
        __half2 h01 = __floats2half2_rn(o.x, o.y);
        __half2 h23 = __floats2half2_rn(o.z, o.w);
        uint2 ph;
        ph.x = *(const unsigned*)&h01;
        ph.y = *(const unsigned*)&h23;
        *(uint2*)hdst = ph;
    }
    __syncthreads();

    // ---- phase 2: mma GEMM on the smem tile ----
    int wm = wid >> 1, wn = wid & 1;
    int sub = lane >> 3, rr8 = lane & 7;
    int arow = wm * 16 + rr8 + (sub & 1) * 8;
    int acol = (sub >> 1) * 8;

    float acc[8][4] = {};
    #pragma unroll
    for (int ks = 0; ks < 8; ks++) {
        unsigned a[4];
        unsigned addr = (unsigned)__cvta_generic_to_shared(&Hs[arow * HS_STRIDE + ks * 16 + acol]);
        ldm_x4(a[0], a[1], a[2], a[3], addr);
        #pragma unroll
        for (int nt = 0; nt < 8; nt++) {
            uint2 b = __ldg(&g_Wf[(ks * 16 + wn * 8 + nt) * 32 + lane]);
            mma16816(acc[nt], a, b.x, b.y);
        }
    }

    int g = lane >> 2, tq = lane & 3;
    int row0 = r0 + wm * 16 + g;
    int row1 = row0 + 8;
    #pragma unroll
    for (int nt = 0; nt < 8; nt++) {
        int col = wn * 64 + nt * 8 + 2 * tq;
        if (row0 < NN) {
            float2 v;
            v.x = elu1(acc[nt][0]);
            v.y = elu1(acc[nt][1]);
            *(float2*)&out[row0 * FF + col] = v;
        }
        if (row1 < NN) {
            float2 v;
            v.x = elu1(acc[nt][2]);
            v.y = elu1(acc[nt][3]);
            *(float2*)&out[row1 * FF + col] = v;
        }
    }
}

// ---------------- launch ----------------
extern "C" void kernel_launch(void* const* d_in, const int* in_sizes, int n_in,
                              void* d_out, int out_size) {
    const float* x    = (const float*)d_in[0];
    const int*   erow = (const int*)  d_in[1];
    const int*   ecol = (const int*)  d_in[2];
    const float* aval = (const float*)d_in[3];
    const int*   tid  = (const int*)  d_in[4];
    const float* M    = (const float*)d_in[5];
    const float* W    = (const float*)d_in[6];
    float*       out  = (float*)d_out;

    k_init        <<<(NN + NWF + 255) / 256, 256>>>(W);
    k_scatter_meff<<<(SCAT_T + MEFF_T + 255) / 256, 256>>>(erow, ecol, aval, x, M);
    k_fix         <<<(NT * 32 + 255) / 256, 256>>>(tid, x);
    k_gg          <<<(NN + GROWS - 1) / GROWS, 256>>>(out);
}

// round 14
// speedup vs baseline: 1.1490x; 1.0488x over previous
#include <cuda_runtime.h>
#include <cuda_fp16.h>
#include <math.h>

#define NN 50000
#define FF 128
#define NE 800000
#define NT 5000
#define NWF 4096               // 8 ksteps * 16 ntiles * 32 lanes
#define SCAT_T (NE / 2)        // 400000 scatter threads (2 edges each)
#define MEFF_T (NN * 32)       // 1600000 meff quad threads
#define MAXDEG 128             // padded CSR row capacity (P(overflow) ~ 1e-68)
#define GROWS 32               // rows per fused block
#define HS_STRIDE 136          // padded fp16 row stride in smem

// ---------------- static device scratch (no allocations allowed) ----------------
struct __align__(16) H2x4 { __half2 me01, me23, mx01, mx23; };
static __device__ H2x4  g_P[NN * 32];          // packed (Me, Mx) fp16, 25.6 MB
static __device__ uint2 g_Wf[NWF];             // W fp16 in mma B-fragment layout, 32 KB
static __device__ int   g_cnt[NN];             // degree counter / CSR fill cursor
static __device__ int2  g_cv[NN * MAXDEG];     // padded CSR (col, val-bits), 51.2 MB

// ---------------- helpers ----------------
__device__ __forceinline__ float sigmoid_fast(float z) {
    return 1.0f / (1.0f + __expf(-z));
}
__device__ __forceinline__ float elu1(float v) {
    return v > 0.0f ? v : expm1f(v);
}
__device__ __forceinline__ void ldm_x4(unsigned& r0, unsigned& r1, unsigned& r2, unsigned& r3,
                                       unsigned addr) {
    asm volatile("ldmatrix.sync.aligned.m8n8.x4.shared.b16 {%0,%1,%2,%3}, [%4];"
                 : "=r"(r0), "=r"(r1), "=r"(r2), "=r"(r3) : "r"(addr));
}
__device__ __forceinline__ void mma16816(float* c, const unsigned* a, unsigned b0, unsigned b1) {
    asm volatile(
        "mma.sync.aligned.m16n8k16.row.col.f32.f16.f16.f32 "
        "{%0,%1,%2,%3}, {%4,%5,%6,%7}, {%8,%9}, {%0,%1,%2,%3};"
        : "+f"(c[0]), "+f"(c[1]), "+f"(c[2]), "+f"(c[3])
        : "r"(a[0]), "r"(a[1]), "r"(a[2]), "r"(a[3]), "r"(b0), "r"(b1));
}
// accumulate one preloaded edge payload: d += Me, h += w * Mx  (fp32, exact)
__device__ __forceinline__ void acc_p(const H2x4& p, float w, float4& d, float4& h) {
    float2 a, b;
    a = __half22float2(p.me01); b = __half22float2(p.me23);
    d.x += a.x; d.y += a.y; d.z += b.x; d.w += b.y;
    a = __half22float2(p.mx01); b = __half22float2(p.mx23);
    h.x += w * a.x; h.y += w * a.y; h.z += w * b.x; h.w += w * b.y;
}
// load+accumulate single edge (tail path)
__device__ __forceinline__ void acc_edge(int col, float w, int lane, float4& d, float4& h) {
    H2x4 p = g_P[col * 32 + lane];
    acc_p(p, w, d, h);
}

// ---------------- kernels ----------------
// L1: zero degree counters + build W mma-fragment table
__global__ void k_init(const float* __restrict__ W) {
    int i = blockIdx.x * blockDim.x + threadIdx.x;
    if (i < NN) g_cnt[i] = 0;
    int j = i - NN;
    if (j >= 0 && j < NWF) {
        int lane = j & 31, ntg = (j >> 5) & 15, ks = j >> 9;
        int n  = ntg * 8 + (lane >> 2);
        int tq = lane & 3;
        int k0 = ks * 16 + tq * 2;
        __half2 b0 = __floats2half2_rn(W[k0 * FF + n],       W[(k0 + 1) * FF + n]);
        __half2 b1 = __floats2half2_rn(W[(k0 + 8) * FF + n], W[(k0 + 9) * FF + n]);
        uint2 o;
        o.x = *(const unsigned*)&b0;
        o.y = *(const unsigned*)&b1;
        g_Wf[j] = o;
    }
}

// L2: single-pass padded-CSR scatter (atomics) overlapped with meff gating (DRAM-bound)
__global__ void k_scatter_meff(const int* __restrict__ erow, const int* __restrict__ ecol,
                               const float* __restrict__ aval,
                               const float* __restrict__ x, const float* __restrict__ M) {
    int gi = blockIdx.x * blockDim.x + threadIdx.x;
    if (gi < SCAT_T) {
        int2   r = ((const int2*)erow)[gi];
        int2   c = ((const int2*)ecol)[gi];
        float2 w = ((const float2*)aval)[gi];
        int p0 = atomicAdd(&g_cnt[r.x], 1);
        if (p0 < MAXDEG) g_cv[r.x * MAXDEG + p0] = make_int2(c.x, __float_as_int(w.x));
        int p1 = atomicAdd(&g_cnt[r.y], 1);
        if (p1 < MAXDEG) g_cv[r.y * MAXDEG + p1] = make_int2(c.y, __float_as_int(w.y));
        return;
    }
    int i = gi - SCAT_T;
    if (i >= MEFF_T) return;
    float4 m  = ((const float4*)M)[i];
    float4 xv = ((const float4*)x)[i];
    float4 me, mx;
    me.x = sigmoid_fast(m.x); me.y = sigmoid_fast(m.y);
    me.z = sigmoid_fast(m.z); me.w = sigmoid_fast(m.w);
    mx.x = me.x * xv.x; mx.y = me.y * xv.y;
    mx.z = me.z * xv.z; mx.w = me.w * xv.w;
    H2x4 p;
    p.me01 = __floats2half2_rn(me.x, me.y);
    p.me23 = __floats2half2_rn(me.z, me.w);
    p.mx01 = __floats2half2_rn(mx.x, mx.y);
    p.mx23 = __floats2half2_rn(mx.z, mx.w);
    g_P[i] = p;
}

// L3: overwrite train rows with (Me=1, Mx=x). Duplicate ids write identical data.
__global__ void k_fix(const int* __restrict__ tid, const float* __restrict__ x) {
    int i = blockIdx.x * blockDim.x + threadIdx.x;
    if (i >= NT * 32) return;
    int node = tid[i >> 5];
    int lane = i & 31;
    float4 xv = *(const float4*)&x[node * FF + lane * 4];
    H2x4 p;
    p.me01 = __floats2half2_rn(1.f, 1.f);
    p.me23 = __floats2half2_rn(1.f, 1.f);
    p.mx01 = __floats2half2_rn(xv.x, xv.y);
    p.mx23 = __floats2half2_rn(xv.z, xv.w);
    g_P[node * 32 + lane] = p;
}

// L4 (fused): gather 32 rows into smem (4 rows/warp), then out = elu(Hs @ W)
// via mma.sync. 256 thr / 8 warps; phase 2 warp tile = 16 rows x 32 cols.
__global__ void __launch_bounds__(256, 5) k_gg(float* __restrict__ out) {
    __shared__ __half Hs[GROWS * HS_STRIDE];
    int r0 = blockIdx.x * GROWS;
    int t  = threadIdx.x;
    int wid = t >> 5, lane = t & 31;

    // ---- phase 1: gather-reduce 4 rows per warp (R10 4-edge inner loop) ----
    for (int rr = 0; rr < 4; rr++) {
        int lr  = wid * 4 + rr;
        int row = r0 + lr;
        __half* hdst = &Hs[lr * HS_STRIDE + lane * 4];
        if (row >= NN) {
            *(uint2*)hdst = make_uint2(0u, 0u);
            continue;
        }
        int deg = g_cnt[row];
        if (deg > MAXDEG) deg = MAXDEG;
        const int4* cp = (const int4*)&g_cv[row * MAXDEG];   // 2 edges per int4
        float4 d = make_float4(0.f, 0.f, 0.f, 0.f);
        float4 h = make_float4(0.f, 0.f, 0.f, 0.f);
        int j = 0;
        for (; j + 3 < deg; j += 4) {       // 4-edge groups
            int q = j >> 1;
            int4 q0 = __ldg(&cp[q]);
            int4 q1 = __ldg(&cp[q + 1]);
            H2x4 p0 = g_P[q0.x * 32 + lane];
            H2x4 p1 = g_P[q0.z * 32 + lane];
            H2x4 p2 = g_P[q1.x * 32 + lane];
            H2x4 p3 = g_P[q1.z * 32 + lane];
            acc_p(p0, __int_as_float(q0.y), d, h);
            acc_p(p1, __int_as_float(q0.w), d, h);
            acc_p(p2, __int_as_float(q1.y), d, h);
            acc_p(p3, __int_as_float(q1.w), d, h);
        }
        if (j + 1 < deg) {                  // 2-edge group
            int4 q0 = __ldg(&cp[j >> 1]);
            H2x4 p0 = g_P[q0.x * 32 + lane];
            H2x4 p1 = g_P[q0.z * 32 + lane];
            acc_p(p0, __int_as_float(q0.y), d, h);
            acc_p(p1, __int_as_float(q0.w), d, h);
            j += 2;
        }
        if (j < deg) {                      // last edge
            int2 cv = __ldg(&g_cv[row * MAXDEG + j]);
            acc_edge(cv.x, __int_as_float(cv.y), lane, d, h);
        }
        float4 o;
        o.x = (d.x != 0.f) ? h.x * __fdividef(1.f, d.x) : 0.f;
        o.y = (d.y != 0.f) ? h.y * __fdividef(1.f, d.y) : 0.f;
        o.z = (d.z != 0.f) ? h.z * __fdividef(1.f, d.z) : 0.f;
        o.w = (d.w != 0.f) ? h.w * __fdividef(1.f, d.w) : 0.f;
        __half2 h01 = __floats2half2_rn(o.x, o.y);
        __half2 h23 = __floats2half2_rn(o.z, o.w);
        uint2 ph;
        ph.x = *(const unsigned*)&h01;
        ph.y = *(const unsigned*)&h23;
        *(uint2*)hdst = ph;
    }
    __syncthreads();

    // ---- phase 2: mma GEMM; warp (wm, wn): rows [wm*16,+16), cols [wn*32,+32) ----
    int wm = wid >> 2, wn = wid & 3;
    int sub = lane >> 3, rr8 = lane & 7;
    int arow = wm * 16 + rr8 + (sub & 1) * 8;
    int acol = (sub >> 1) * 8;

    float acc[4][4] = {};
    #pragma unroll
    for (int ks = 0; ks < 8; ks++) {
        unsigned a[4];
        unsigned addr = (unsigned)__cvta_generic_to_shared(&Hs[arow * HS_STRIDE + ks * 16 + acol]);
        ldm_x4(a[0], a[1], a[2], a[3], addr);
        #pragma unroll
        for (int nt = 0; nt < 4; nt++) {
            uint2 b = __ldg(&g_Wf[(ks * 16 + wn * 4 + nt) * 32 + lane]);
            mma16816(acc[nt], a, b.x, b.y);
        }
    }

    int g = lane >> 2, tq = lane & 3;
    int row0 = r0 + wm * 16 + g;
    int row1 = row0 + 8;
    #pragma unroll
    for (int nt = 0; nt < 4; nt++) {
        int col = wn * 32 + nt * 8 + 2 * tq;
        if (row0 < NN) {
            float2 v;
            v.x = elu1(acc[nt][0]);
            v.y = elu1(acc[nt][1]);
            *(float2*)&out[row0 * FF + col] = v;
        }
        if (row1 < NN) {
            float2 v;
            v.x = elu1(acc[nt][2]);
            v.y = elu1(acc[nt][3]);
            *(float2*)&out[row1 * FF + col] = v;
        }
    }
}

// ---------------- launch ----------------
extern "C" void kernel_launch(void* const* d_in, const int* in_sizes, int n_in,
                              void* d_out, int out_size) {
    const float* x    = (const float*)d_in[0];
    const int*   erow = (const int*)  d_in[1];
    const int*   ecol = (const int*)  d_in[2];
    const float* aval = (const float*)d_in[3];
    const int*   tid  = (const int*)  d_in[4];
    const float* M    = (const float*)d_in[5];
    const float* W    = (const float*)d_in[6];
    float*       out  = (float*)d_out;

    k_init        <<<(NN + NWF + 255) / 256, 256>>>(W);
    k_scatter_meff<<<(SCAT_T + MEFF_T + 255) / 256, 256>>>(erow, ecol, aval, x, M);
    k_fix         <<<(NT * 32 + 255) / 256, 256>>>(tid, x);
    k_gg          <<<(NN + GROWS - 1) / GROWS, 256>>>(out);
}

// round 15
// speedup vs baseline: 1.2705x; 1.1058x over previous
#include <cuda_runtime.h>
#include <cuda_fp16.h>
#include <math.h>

#define NN 50000
#define FF 128
#define NE 800000
#define NT 5000
#define NWF 4096               // 8 ksteps * 16 ntiles * 32 lanes
#define SCAT_T (NE / 2)        // 400000 scatter threads (2 edges each)
#define MEFF_T (NN * 32)       // 1600000 meff quad threads
#define MAXDEG 128             // padded CSR row capacity (P(overflow) ~ 1e-68)
#define GROWS 32               // rows per fused block
#define HS_STRIDE 136          // padded fp16 row stride in smem

// ---------------- static device scratch (no allocations allowed) ----------------
struct __align__(16) H2x4 { __half2 me01, me23, mx01, mx23; };
static __device__ H2x4  g_P[NN * 32];          // packed (Me, Mx) fp16, 25.6 MB
static __device__ uint2 g_Wf[NWF];             // W fp16 in mma B-fragment layout, 32 KB
static __device__ int   g_cnt[NN];             // degree counter / CSR fill cursor
static __device__ int2  g_cv[NN * MAXDEG];     // padded CSR (col, val-bits), 51.2 MB

// ---------------- helpers ----------------
__device__ __forceinline__ float sigmoid_fast(float z) {
    return 1.0f / (1.0f + __expf(-z));
}
__device__ __forceinline__ float elu1(float v) {
    return v > 0.0f ? v : expm1f(v);
}
__device__ __forceinline__ void ldm_x4(unsigned& r0, unsigned& r1, unsigned& r2, unsigned& r3,
                                       unsigned addr) {
    asm volatile("ldmatrix.sync.aligned.m8n8.x4.shared.b16 {%0,%1,%2,%3}, [%4];"
                 : "=r"(r0), "=r"(r1), "=r"(r2), "=r"(r3) : "r"(addr));
}
__device__ __forceinline__ void mma16816(float* c, const unsigned* a, unsigned b0, unsigned b1) {
    asm volatile(
        "mma.sync.aligned.m16n8k16.row.col.f32.f16.f16.f32 "
        "{%0,%1,%2,%3}, {%4,%5,%6,%7}, {%8,%9}, {%0,%1,%2,%3};"
        : "+f"(c[0]), "+f"(c[1]), "+f"(c[2]), "+f"(c[3])
        : "r"(a[0]), "r"(a[1]), "r"(a[2]), "r"(a[3]), "r"(b0), "r"(b1));
}
// fp32 single-edge accumulate (tail path, exact)
__device__ __forceinline__ void acc_edge(int col, float w, int lane, float4& d, float4& h) {
    H2x4 p = g_P[col * 32 + lane];
    float2 a, b;
    a = __half22float2(p.me01); b = __half22float2(p.me23);
    d.x += a.x; d.y += a.y; d.z += b.x; d.w += b.y;
    a = __half22float2(p.mx01); b = __half22float2(p.mx23);
    h.x += w * a.x; h.y += w * a.y; h.z += w * b.x; h.w += w * b.y;
}
// fp16 packed accumulate of a preloaded payload (hot path)
__device__ __forceinline__ void acc_ph(const H2x4& p, float w,
                                       __half2& d01, __half2& d23,
                                       __half2& h01, __half2& h23) {
    __half2 wh = __float2half2_rn(w);
    d01 = __hadd2(d01, p.me01);
    d23 = __hadd2(d23, p.me23);
    h01 = __hfma2(p.mx01, wh, h01);
    h23 = __hfma2(p.mx23, wh, h23);
}

// ---------------- kernels ----------------
// L1: zero degree counters + build W mma-fragment table
__global__ void k_init(const float* __restrict__ W) {
    int i = blockIdx.x * blockDim.x + threadIdx.x;
    if (i < NN) g_cnt[i] = 0;
    int j = i - NN;
    if (j >= 0 && j < NWF) {
        int lane = j & 31, ntg = (j >> 5) & 15, ks = j >> 9;
        int n  = ntg * 8 + (lane >> 2);
        int tq = lane & 3;
        int k0 = ks * 16 + tq * 2;
        __half2 b0 = __floats2half2_rn(W[k0 * FF + n],       W[(k0 + 1) * FF + n]);
        __half2 b1 = __floats2half2_rn(W[(k0 + 8) * FF + n], W[(k0 + 9) * FF + n]);
        uint2 o;
        o.x = *(const unsigned*)&b0;
        o.y = *(const unsigned*)&b1;
        g_Wf[j] = o;
    }
}

// L2: single-pass padded-CSR scatter (atomics) overlapped with meff gating (DRAM-bound)
__global__ void k_scatter_meff(const int* __restrict__ erow, const int* __restrict__ ecol,
                               const float* __restrict__ aval,
                               const float* __restrict__ x, const float* __restrict__ M) {
    int gi = blockIdx.x * blockDim.x + threadIdx.x;
    if (gi < SCAT_T) {
        int2   r = ((const int2*)erow)[gi];
        int2   c = ((const int2*)ecol)[gi];
        float2 w = ((const float2*)aval)[gi];
        int p0 = atomicAdd(&g_cnt[r.x], 1);
        if (p0 < MAXDEG) g_cv[r.x * MAXDEG + p0] = make_int2(c.x, __float_as_int(w.x));
        int p1 = atomicAdd(&g_cnt[r.y], 1);
        if (p1 < MAXDEG) g_cv[r.y * MAXDEG + p1] = make_int2(c.y, __float_as_int(w.y));
        return;
    }
    int i = gi - SCAT_T;
    if (i >= MEFF_T) return;
    float4 m  = ((const float4*)M)[i];
    float4 xv = ((const float4*)x)[i];
    float4 me, mx;
    me.x = sigmoid_fast(m.x); me.y = sigmoid_fast(m.y);
    me.z = sigmoid_fast(m.z); me.w = sigmoid_fast(m.w);
    mx.x = me.x * xv.x; mx.y = me.y * xv.y;
    mx.z = me.z * xv.z; mx.w = me.w * xv.w;
    H2x4 p;
    p.me01 = __floats2half2_rn(me.x, me.y);
    p.me23 = __floats2half2_rn(me.z, me.w);
    p.mx01 = __floats2half2_rn(mx.x, mx.y);
    p.mx23 = __floats2half2_rn(mx.z, mx.w);
    g_P[i] = p;
}

// L3: overwrite train rows with (Me=1, Mx=x). Duplicate ids write identical data.
__global__ void k_fix(const int* __restrict__ tid, const float* __restrict__ x) {
    int i = blockIdx.x * blockDim.x + threadIdx.x;
    if (i >= NT * 32) return;
    int node = tid[i >> 5];
    int lane = i & 31;
    float4 xv = *(const float4*)&x[node * FF + lane * 4];
    H2x4 p;
    p.me01 = __floats2half2_rn(1.f, 1.f);
    p.me23 = __floats2half2_rn(1.f, 1.f);
    p.mx01 = __floats2half2_rn(xv.x, xv.y);
    p.mx23 = __floats2half2_rn(xv.z, xv.w);
    g_P[node * 32 + lane] = p;
}

// L4 (fused): gather 32 rows into smem (4 rows/warp, fp16 group accumulation
// flushed to fp32 every 4 edges), then out = elu(Hs @ W) via mma.sync.
__global__ void __launch_bounds__(256, 6) k_gg(float* __restrict__ out) {
    __shared__ __half Hs[GROWS * HS_STRIDE];
    int r0 = blockIdx.x * GROWS;
    int t  = threadIdx.x;
    int wid = t >> 5, lane = t & 31;

    // ---- phase 1: gather-reduce 4 rows per warp ----
    for (int rr = 0; rr < 4; rr++) {
        int lr  = wid * 4 + rr;
        int row = r0 + lr;
        __half* hdst = &Hs[lr * HS_STRIDE + lane * 4];
        if (row >= NN) {
            *(uint2*)hdst = make_uint2(0u, 0u);
            continue;
        }
        int deg = g_cnt[row];
        if (deg > MAXDEG) deg = MAXDEG;
        const int4* cp = (const int4*)&g_cv[row * MAXDEG];   // 2 edges per int4
        float4 d = make_float4(0.f, 0.f, 0.f, 0.f);
        float4 h = make_float4(0.f, 0.f, 0.f, 0.f);
        int j = 0;
        for (; j + 3 < deg; j += 4) {       // 4-edge groups, fp16 partial sums
            int q = j >> 1;
            int4 q0 = __ldg(&cp[q]);
            int4 q1 = __ldg(&cp[q + 1]);
            H2x4 p0 = g_P[q0.x * 32 + lane];
            H2x4 p1 = g_P[q0.z * 32 + lane];
            H2x4 p2 = g_P[q1.x * 32 + lane];
            H2x4 p3 = g_P[q1.z * 32 + lane];
            __half2 z   = __float2half2_rn(0.f);
            __half2 d01 = z, d23 = z, h01 = z, h23 = z;
            acc_ph(p0, __int_as_float(q0.y), d01, d23, h01, h23);
            acc_ph(p1, __int_as_float(q0.w), d01, d23, h01, h23);
            acc_ph(p2, __int_as_float(q1.y), d01, d23, h01, h23);
            acc_ph(p3, __int_as_float(q1.w), d01, d23, h01, h23);
            float2 f;
            f = __half22float2(d01); d.x += f.x; d.y += f.y;
            f = __half22float2(d23); d.z += f.x; d.w += f.y;
            f = __half22float2(h01); h.x += f.x; h.y += f.y;
            f = __half22float2(h23); h.z += f.x; h.w += f.y;
        }
        for (; j < deg; ++j) {              // tail: exact fp32
            int2 cv = __ldg(&g_cv[row * MAXDEG + j]);
            acc_edge(cv.x, __int_as_float(cv.y), lane, d, h);
        }
        float4 o;
        o.x = (d.x != 0.f) ? h.x * __fdividef(1.f, d.x) : 0.f;
        o.y = (d.y != 0.f) ? h.y * __fdividef(1.f, d.y) : 0.f;
        o.z = (d.z != 0.f) ? h.z * __fdividef(1.f, d.z) : 0.f;
        o.w = (d.w != 0.f) ? h.w * __fdividef(1.f, d.w) : 0.f;
        __half2 h01 = __floats2half2_rn(o.x, o.y);
        __half2 h23 = __floats2half2_rn(o.z, o.w);
        uint2 ph;
        ph.x = *(const unsigned*)&h01;
        ph.y = *(const unsigned*)&h23;
        *(uint2*)hdst = ph;
    }
    __syncthreads();

    // ---- phase 2: mma GEMM; warp (wm, wn): rows [wm*16,+16), cols [wn*32,+32) ----
    int wm = wid >> 2, wn = wid & 3;
    int sub = lane >> 3, rr8 = lane & 7;
    int arow = wm * 16 + rr8 + (sub & 1) * 8;
    int acol = (sub >> 1) * 8;

    float acc[4][4] = {};
    #pragma unroll
    for (int ks = 0; ks < 8; ks++) {
        unsigned a[4];
        unsigned addr = (unsigned)__cvta_generic_to_shared(&Hs[arow * HS_STRIDE + ks * 16 + acol]);
        ldm_x4(a[0], a[1], a[2], a[3], addr);
        #pragma unroll
        for (int nt = 0; nt < 4; nt++) {
            uint2 b = __ldg(&g_Wf[(ks * 16 + wn * 4 + nt) * 32 + lane]);
            mma16816(acc[nt], a, b.x, b.y);
        }
    }

    int g = lane >> 2, tq = lane & 3;
    int row0 = r0 + wm * 16 + g;
    int row1 = row0 + 8;
    #pragma unroll
    for (int nt = 0; nt < 4; nt++) {
        int col = wn * 32 + nt * 8 + 2 * tq;
        if (row0 < NN) {
            float2 v;
            v.x = elu1(acc[nt][0]);
            v.y = elu1(acc[nt][1]);
            *(float2*)&out[row0 * FF + col] = v;
        }
        if (row1 < NN) {
            float2 v;
            v.x = elu1(acc[nt][2]);
            v.y = elu1(acc[nt][3]);
            *(float2*)&out[row1 * FF + col] = v;
        }
    }
}

// ---------------- launch ----------------
extern "C" void kernel_launch(void* const* d_in, const int* in_sizes, int n_in,
                              void* d_out, int out_size) {
    const float* x    = (const float*)d_in[0];
    const int*   erow = (const int*)  d_in[1];
    const int*   ecol = (const int*)  d_in[2];
    const float* aval = (const float*)d_in[3];
    const int*   tid  = (const int*)  d_in[4];
    const float* M    = (const float*)d_in[5];
    const float* W    = (const float*)d_in[6];
    float*       out  = (float*)d_out;

    k_init        <<<(NN + NWF + 255) / 256, 256>>>(W);
    k_scatter_meff<<<(SCAT_T + MEFF_T + 255) / 256, 256>>>(erow, ecol, aval, x, M);
    k_fix         <<<(NT * 32 + 255) / 256, 256>>>(tid, x);
    k_gg          <<<(NN + GROWS - 1) / GROWS, 256>>>(out);
}